// round 8
// baseline (speedup 1.0000x reference)
#include <cuda_runtime.h>
#include <math.h>

#define SEQ   512
#define BATCH 64
#define EMB   300
#define HID   512
#define GATES 2048   // 4*HID
#define NTAG  12
#define NEGV  (-10000.0f)
#define START_TAG 10
#define STOP_TAG  11

// ---------------- scratch (device globals; no allocation) ----------------
__device__ float g_xw[2][SEQ][GATES][BATCH];   // pre-activations x@W_ih.T+b
__device__ float g_hf[SEQ][HID][BATCH];        // forward hidden states [s][u][b]
__device__ float g_hb[SEQ][HID][BATCH];        // backward hidden states in SCAN order
__device__ float g_hinit[2][HID][BATCH];       // transposed h0
__device__ float g_Wt_ih[2][EMB][GATES];       // W_ih transposed [e][j]
__device__ float g_Wout_t[2 * HID][NTAG];      // W_out transposed [k][t]
__device__ float g_feats[SEQ][BATCH][NTAG];
__device__ float g_crf_part[8];
__device__ unsigned g_flag[2][64];             // per-block step flags

// ---------------- f32x2 helpers ----------------
__device__ __forceinline__ unsigned long long splat2(float x) {
    unsigned long long r; unsigned u = __float_as_uint(x);
    asm("mov.b64 %0, {%1, %1};" : "=l"(r) : "r"(u));
    return r;
}
__device__ __forceinline__ void ffma2(unsigned long long& d,
                                      unsigned long long a,
                                      unsigned long long b) {
    asm("fma.rn.f32x2 %0, %1, %2, %0;" : "+l"(d) : "l"(a), "l"(b));
}
__device__ __forceinline__ unsigned long long addf2(unsigned long long a,
                                                    unsigned long long b) {
    unsigned long long r;
    asm("add.rn.f32x2 %0, %1, %2;" : "=l"(r) : "l"(a), "l"(b));
    return r;
}
__device__ __forceinline__ float2 unpack2(unsigned long long v) {
    unsigned lo, hi;
    asm("mov.b64 {%0, %1}, %2;" : "=r"(lo), "=r"(hi) : "l"(v));
    float2 f; f.x = __uint_as_float(lo); f.y = __uint_as_float(hi);
    return f;
}
__device__ __forceinline__ float sigf(float x) { return 1.f / (1.f + __expf(-x)); }
__device__ __forceinline__ float tanhfast(float x) { return 2.f / (1.f + __expf(-2.f * x)) - 1.f; }

// ---------------- prep: transposes + state init + flag reset ----------------
__global__ void prep_kernel(const float* Wif, const float* Wib, const float* h0,
                            const float* Wout) {
    if (blockIdx.x == 0 && threadIdx.x < 128)
        ((unsigned*)g_flag)[threadIdx.x] = 0;
    const int N_IH = 2 * EMB * GATES;
    const int N_H  = 2 * HID * BATCH;
    const int N_WO = NTAG * 2 * HID;
    const int total = N_IH + N_H + N_WO;
    for (int idx = blockIdx.x * blockDim.x + threadIdx.x; idx < total;
         idx += gridDim.x * blockDim.x) {
        int i = idx;
        if (i < N_IH) {
            int d = i / (EMB * GATES);
            int r = i % (EMB * GATES);
            int e = r / GATES, j = r % GATES;
            const float* W = d ? Wib : Wif;
            g_Wt_ih[d][e][j] = W[j * EMB + e];
        } else if ((i -= N_IH) < N_H) {
            int d = i / (HID * BATCH);
            int r = i % (HID * BATCH);
            int u = r / BATCH, b = r % BATCH;
            g_hinit[d][u][b] = h0[(d * BATCH + b) * HID + u];
        } else {
            i -= N_H;
            int k = i / NTAG, t = i % NTAG;
            g_Wout_t[k][t] = Wout[t * (2 * HID) + k];
        }
    }
}

// ---------------- input GEMM (f32x2) ----------------
__global__ __launch_bounds__(256)
void xw_gemm(const int* __restrict__ tokens,
             const float* __restrict__ W_emb,
             const float* __restrict__ b_f,
             const float* __restrict__ b_b) {
    int dir = blockIdx.z;
    int s   = blockIdx.y;
    int n0  = blockIdx.x * 128;
    __shared__ float As[16][64];
    __shared__ float Bs[16][128];
    __shared__ int   tokS[64];
    int tid = threadIdx.x;
    if (tid < 64) {
        int srow = dir ? (SEQ - 1 - s) : s;
        tokS[tid] = tokens[tid * SEQ + srow];
    }
    __syncthreads();
    int c0 = (tid >> 3) * 4;
    int b0 = (tid & 7) * 8;
    unsigned long long acc[4][4] = {};
    for (int k0 = 0; k0 < 304; k0 += 16) {
        {
            int b = tid & 63, kk4 = (tid >> 6) * 4;
            int k = k0 + kk4;
            float4 v = {0.f, 0.f, 0.f, 0.f};
            if (k + 3 < EMB)
                v = *(const float4*)(W_emb + (size_t)tokS[b] * EMB + k);
            As[kk4 + 0][b] = v.x;
            As[kk4 + 1][b] = v.y;
            As[kk4 + 2][b] = v.z;
            As[kk4 + 3][b] = v.w;
        }
#pragma unroll
        for (int r = 0; r < 2; r++) {
            int idx = tid + 256 * r;
            int kk = idx >> 5, cg = idx & 31;
            float4 w = {0.f, 0.f, 0.f, 0.f};
            if (k0 + kk < EMB)
                w = *(const float4*)&g_Wt_ih[dir][k0 + kk][n0 + cg * 4];
            *(float4*)&Bs[kk][cg * 4] = w;
        }
        __syncthreads();
#pragma unroll
        for (int kk = 0; kk < 16; kk++) {
            float4 wv = *(const float4*)&Bs[kk][c0];
            unsigned long long w0 = splat2(wv.x), w1 = splat2(wv.y);
            unsigned long long w2 = splat2(wv.z), w3 = splat2(wv.w);
            ulonglong2 xA = *(const ulonglong2*)&As[kk][b0];
            ulonglong2 xB = *(const ulonglong2*)&As[kk][b0 + 4];
            ffma2(acc[0][0], xA.x, w0); ffma2(acc[0][1], xA.y, w0);
            ffma2(acc[0][2], xB.x, w0); ffma2(acc[0][3], xB.y, w0);
            ffma2(acc[1][0], xA.x, w1); ffma2(acc[1][1], xA.y, w1);
            ffma2(acc[1][2], xB.x, w1); ffma2(acc[1][3], xB.y, w1);
            ffma2(acc[2][0], xA.x, w2); ffma2(acc[2][1], xA.y, w2);
            ffma2(acc[2][2], xB.x, w2); ffma2(acc[2][3], xB.y, w2);
            ffma2(acc[3][0], xA.x, w3); ffma2(acc[3][1], xA.y, w3);
            ffma2(acc[3][2], xB.x, w3); ffma2(acc[3][3], xB.y, w3);
        }
        __syncthreads();
    }
    const float* bias = dir ? b_b : b_f;
#pragma unroll
    for (int cc = 0; cc < 4; cc++) {
        int j = n0 + c0 + cc;
        float bv = bias[j];
        float2 p0 = unpack2(acc[cc][0]), p1 = unpack2(acc[cc][1]);
        float2 p2 = unpack2(acc[cc][2]), p3 = unpack2(acc[cc][3]);
        float4 o0 = {p0.x + bv, p0.y + bv, p1.x + bv, p1.y + bv};
        float4 o1 = {p2.x + bv, p2.y + bv, p3.x + bv, p3.y + bv};
        *(float4*)&g_xw[dir][s][j][b0] = o0;
        *(float4*)&g_xw[dir][s][j][b0 + 4] = o1;
    }
}

// ---------------- persistent fused BiLSTM (512 thr, 4-way K-split, flag barrier) ----
// 128 blocks (64/dir) x 512 thr. Block = 8 units x 4 gates (32 cols) x 64 batch.
// Thread = (kgroup 0..3, col-pair 0..15, octet 0..7): 2 cols x 8 batch x 128 k.
#define SWS 513
__global__ __launch_bounds__(512, 1)
void lstm_persistent(const float* __restrict__ Whf, const float* __restrict__ Whb,
                     const float* __restrict__ c0in) {
    extern __shared__ float smem[];
    float2* sW = (float2*)smem;               // [16 cp][SWS] = 65,664 B
    float*  sH = smem + 16 * SWS * 2;         // 2 bufs x [4 kg][64 k][64 b] = 131,072 B

    int tid = threadIdx.x;
    int bid = blockIdx.x;
    int dir = bid >> 6;
    int u0  = (bid & 63) * 8;
    const float* Whh = dir ? Whb : Whf;

    // stage W pairs: sW[cp][k] = (W[col 2cp][k], W[col 2cp+1][k])
    for (int l = tid; l < 16 * 512; l += 512) {
        int cp = l >> 9, k = l & 511;
        int ca = cp * 2, cb = ca + 1;
        int ja = (ca >> 3) * HID + u0 + (ca & 7);
        int jb = (cb >> 3) * HID + u0 + (cb & 7);
        float2 v;
        v.x = Whh[ja * HID + k];
        v.y = Whh[jb * HID + k];
        sW[cp * SWS + k] = v;
    }

    int kg  = tid >> 7;                // k-group 0..3 (128 k each)
    int cp  = (tid >> 3) & 15;         // col-pair 0..15
    int b0  = (tid & 7) * 8;           // batch base

    // cell state: 1 value/thread (p = tid): uu = tid>>6, b = tid&63
    float cst;
    {
        int uu = tid >> 6, b = tid & 63;
        cst = c0in[(dir * BATCH + b) * HID + (u0 + uu)];
    }
    __syncthreads();

    const float2* wrow = sW + cp * SWS;
    int ca = cp * 2, cb = ca + 1;
    int j0 = (ca >> 3) * HID + u0 + (ca & 7);
    int j1 = (cb >> 3) * HID + u0 + (cb & 7);

    for (int s = 0; s < SEQ; s++) {
        unsigned target = (unsigned)(s + 1);
        const float* hprev = (s == 0) ? &g_hinit[dir][0][0]
                                      : (dir ? &g_hb[s - 1][0][0] : &g_hf[s - 1][0][0]);
        // hoist xw loads for reducer group (kg==0): 2 cols x 8 batch
        float4 xwA0, xwA1, xwB0, xwB1;
        if (kg == 0) {
            xwA0 = *(const float4*)&g_xw[dir][s][j0][b0];
            xwA1 = *(const float4*)&g_xw[dir][s][j0][b0 + 4];
            xwB0 = *(const float4*)&g_xw[dir][s][j1][b0];
            xwB1 = *(const float4*)&g_xw[dir][s][j1][b0 + 4];
        }

        // stage half 0: [4 kg][k 0..63][64 b] -> buf0; 8 float4/thread
#pragma unroll
        for (int r = 0; r < 8; r++) {
            int m = tid + 512 * r;                // f4 idx 0..4095
            int kgs = m >> 10;
            int rem = m & 1023;
            int kk = rem >> 4, b4 = rem & 15;
            float4 v = *(const float4*)(hprev + (kgs * 128 + kk) * BATCH + b4 * 4);
            *(float4*)(sH + m * 4) = v;
        }
        __syncthreads();

        unsigned long long acc[2][4] = {};
        // prefetch half 1
        float4 pf[8];
#pragma unroll
        for (int r = 0; r < 8; r++) {
            int m = tid + 512 * r;
            int kgs = m >> 10;
            int rem = m & 1023;
            int kk = rem >> 4, b4 = rem & 15;
            pf[r] = *(const float4*)(hprev + (kgs * 128 + 64 + kk) * BATCH + b4 * 4);
        }
        // compute half 0
        {
            const float* hb = sH + kg * 4096;
            const float2* wsub = wrow + kg * 128;
#pragma unroll 16
            for (int kk = 0; kk < 64; kk++) {
                float2 wv = wsub[kk];
                ulonglong2 hA = *(const ulonglong2*)(hb + kk * BATCH + b0);
                ulonglong2 hB = *(const ulonglong2*)(hb + kk * BATCH + b0 + 4);
                unsigned long long w0 = splat2(wv.x), w1 = splat2(wv.y);
                ffma2(acc[0][0], hA.x, w0); ffma2(acc[0][1], hA.y, w0);
                ffma2(acc[0][2], hB.x, w0); ffma2(acc[0][3], hB.y, w0);
                ffma2(acc[1][0], hA.x, w1); ffma2(acc[1][1], hA.y, w1);
                ffma2(acc[1][2], hB.x, w1); ffma2(acc[1][3], hB.y, w1);
            }
        }
        // park half 1
#pragma unroll
        for (int r = 0; r < 8; r++) {
            int m = tid + 512 * r;
            *(float4*)(sH + 16384 + m * 4) = pf[r];
        }
        __syncthreads();
        // compute half 1
        {
            const float* hb = sH + 16384 + kg * 4096;
            const float2* wsub = wrow + kg * 128 + 64;
#pragma unroll 16
            for (int kk = 0; kk < 64; kk++) {
                float2 wv = wsub[kk];
                ulonglong2 hA = *(const ulonglong2*)(hb + kk * BATCH + b0);
                ulonglong2 hB = *(const ulonglong2*)(hb + kk * BATCH + b0 + 4);
                unsigned long long w0 = splat2(wv.x), w1 = splat2(wv.y);
                ffma2(acc[0][0], hA.x, w0); ffma2(acc[0][1], hA.y, w0);
                ffma2(acc[0][2], hB.x, w0); ffma2(acc[0][3], hB.y, w0);
                ffma2(acc[1][0], hA.x, w1); ffma2(acc[1][1], hA.y, w1);
                ffma2(acc[1][2], hB.x, w1); ffma2(acc[1][3], hB.y, w1);
            }
        }
        // park partials (kg 1-3) into buf0 region: slot = tid-128, 8 u64 each
        unsigned long long* ap = &acc[0][0];
        if (kg != 0) {
            ulonglong2* pp = (ulonglong2*)((unsigned long long*)sH + (size_t)(tid - 128) * 8);
#pragma unroll
            for (int i = 0; i < 4; i++)
                pp[i] = *(ulonglong2*)&ap[i * 2];
        }
        __syncthreads();
        float* sG = sH + 8192;                     // gates: beyond park area (6144)
        if (kg == 0) {
#pragma unroll
            for (int g = 0; g < 3; g++) {
                const ulonglong2* pp =
                    (const ulonglong2*)((unsigned long long*)sH + (size_t)(tid + g * 128) * 8);
#pragma unroll
                for (int i = 0; i < 4; i++) {
                    ulonglong2 v = pp[i];
                    ap[i * 2 + 0] = addf2(ap[i * 2 + 0], v.x);
                    ap[i * 2 + 1] = addf2(ap[i * 2 + 1], v.y);
                }
            }
            float2 p0 = unpack2(acc[0][0]), p1 = unpack2(acc[0][1]);
            float2 p2 = unpack2(acc[0][2]), p3 = unpack2(acc[0][3]);
            float2 q0 = unpack2(acc[1][0]), q1 = unpack2(acc[1][1]);
            float2 q2 = unpack2(acc[1][2]), q3 = unpack2(acc[1][3]);
            float4 oA0 = {p0.x + xwA0.x, p0.y + xwA0.y, p1.x + xwA0.z, p1.y + xwA0.w};
            float4 oA1 = {p2.x + xwA1.x, p2.y + xwA1.y, p3.x + xwA1.z, p3.y + xwA1.w};
            float4 oB0 = {q0.x + xwB0.x, q0.y + xwB0.y, q1.x + xwB0.z, q1.y + xwB0.w};
            float4 oB1 = {q2.x + xwB1.x, q2.y + xwB1.y, q3.x + xwB1.z, q3.y + xwB1.w};
            *(float4*)(sG + ca * 68 + b0) = oA0;
            *(float4*)(sG + ca * 68 + b0 + 4) = oA1;
            *(float4*)(sG + cb * 68 + b0) = oB0;
            *(float4*)(sG + cb * 68 + b0 + 4) = oB1;
        }
        __syncthreads();

        // pointwise: 1 elem/thread; c in registers
        float* hout = dir ? &g_hb[s][0][0] : &g_hf[s][0][0];
        {
            int uu = tid >> 6, b = tid & 63;
            float gi = sG[(uu) * 68 + b];
            float gf = sG[(8 + uu) * 68 + b];
            float gg = sG[(16 + uu) * 68 + b];
            float go = sG[(24 + uu) * 68 + b];
            float iv = sigf(gi), fv = sigf(gf), ov = sigf(go);
            float c = fv * cst + iv * tanhfast(gg);
            cst = c;
            hout[(u0 + uu) * BATCH + b] = ov * tanhfast(c);
        }
        __syncthreads();   // all hout STGs issued + CTA-visible

        // flag-array barrier: parallel arrival, warp-0 poll
        if (tid == 0) {
            asm volatile("fence.acq_rel.gpu;" ::: "memory");
            asm volatile("st.relaxed.gpu.global.u32 [%0], %1;"
                         :: "l"(&g_flag[dir][bid & 63]), "r"(target) : "memory");
        }
        if (tid < 32) {
            const unsigned* f1 = &g_flag[dir][tid];
            const unsigned* f2 = f1 + 32;
            unsigned t1, t2;
            do {
                asm volatile("ld.relaxed.gpu.global.u32 %0, [%1];" : "=r"(t1) : "l"(f1));
                asm volatile("ld.relaxed.gpu.global.u32 %0, [%1];" : "=r"(t2) : "l"(f2));
            } while (!__all_sync(0xffffffffu, (t1 >= target) && (t2 >= target)));
            asm volatile("fence.acq_rel.gpu;" ::: "memory");
        }
        __syncthreads();
    }
}

// ---------------- feats: K-split, 12 independent chains per thread ----------------
__global__ __launch_bounds__(256)
void feats_kernel(const float* __restrict__ b_out) {
    int s = blockIdx.x;
    int tid = threadIdx.x;
    int b = tid & 63;
    int slice = tid >> 6;
    __shared__ float sred[256][NTAG];
    float a[NTAG];
#pragma unroll
    for (int t = 0; t < NTAG; t++) a[t] = 0.f;

    int base = slice * 256;
    const float* hbase = (base < HID) ? &g_hf[s][base][0]
                                      : &g_hb[SEQ - 1 - s][base - HID][0];
#pragma unroll 4
    for (int k = 0; k < 256; k++) {
        float h = hbase[k * BATCH + b];
        int kg = base + k;
        float4 w0 = *(const float4*)&g_Wout_t[kg][0];
        float4 w1 = *(const float4*)&g_Wout_t[kg][4];
        float4 w2 = *(const float4*)&g_Wout_t[kg][8];
        a[0] += h * w0.x;  a[1] += h * w0.y;  a[2]  += h * w0.z;  a[3]  += h * w0.w;
        a[4] += h * w1.x;  a[5] += h * w1.y;  a[6]  += h * w1.z;  a[7]  += h * w1.w;
        a[8] += h * w2.x;  a[9] += h * w2.y;  a[10] += h * w2.z;  a[11] += h * w2.w;
    }
#pragma unroll
    for (int t = 0; t < NTAG; t++) sred[tid][t] = a[t];
    __syncthreads();
    if (tid < 64) {
#pragma unroll
        for (int t = 0; t < NTAG; t++) {
            float v = b_out[t] + sred[tid][t] + sred[64 + tid][t]
                    + sred[128 + tid][t] + sred[192 + tid][t];
            g_feats[s][tid][t] = v;
        }
    }
}

// ---------------- CRF forward: 8 blocks x 8 batches, feats prefetch ----------------
__global__ __launch_bounds__(96)
void crf_kernel(const int* __restrict__ lengths,
                const float* __restrict__ trans) {
    __shared__ float alpha[8][NTAG];
    __shared__ float tr[NTAG][NTAG];
    __shared__ float termS[8][NTAG];
    int tid = threadIdx.x;
    int b = tid / NTAG, t = tid % NTAG;
    int bg = blockIdx.x * 8 + b;
    for (int l = tid; l < NTAG * NTAG; l += 96)
        tr[l / NTAG][l % NTAG] = trans[l];
    alpha[b][t] = (t == START_TAG) ? 0.f : NEGV;
    int len = lengths[bg];
    __syncthreads();
    float fcur = g_feats[0][bg][t];
    for (int s = 0; s < SEQ; s++) {
        float fnext = (s + 1 < SEQ) ? g_feats[s + 1][bg][t] : 0.f;
        float v[NTAG];
        float mx = -1e30f;
#pragma unroll
        for (int p = 0; p < NTAG; p++) {
            v[p] = alpha[b][p] + tr[t][p];
            mx = fmaxf(mx, v[p]);
        }
        float sum = 0.f;
#pragma unroll
        for (int p = 0; p < NTAG; p++) sum += __expf(v[p] - mx);
        float newv = mx + __logf(sum) + fcur;
        float keep = alpha[b][t];
        float nv = (s < len) ? newv : keep;
        __syncthreads();
        alpha[b][t] = nv;
        __syncthreads();
        fcur = fnext;
    }
    termS[b][t] = alpha[b][t] + tr[STOP_TAG][t];
    __syncthreads();
    if (t == 0) {
        float mx = -1e30f;
#pragma unroll
        for (int p = 0; p < NTAG; p++) mx = fmaxf(mx, termS[b][p]);
        float sum = 0.f;
#pragma unroll
        for (int p = 0; p < NTAG; p++) sum += __expf(termS[b][p] - mx);
        termS[b][0] = mx + __logf(sum);
    }
    __syncthreads();
    if (tid == 0) {
        float s2 = 0.f;
        for (int i = 0; i < 8; i++) s2 += termS[i][0];
        g_crf_part[blockIdx.x] = s2;
    }
}

__global__ void crf_finish(float* __restrict__ out) {
    float s = 0.f;
    for (int i = 0; i < 8; i++) s += g_crf_part[i];
    out[0] = s / (float)BATCH;
}

// ---------------- launch ----------------
extern "C" void kernel_launch(void* const* d_in, const int* in_sizes, int n_in,
                              void* d_out, int out_size) {
    const int*   tokens  = (const int*)  d_in[0];
    const int*   lengths = (const int*)  d_in[1];
    const float* W_emb   = (const float*)d_in[2];
    const float* W_ih_f  = (const float*)d_in[3];
    const float* W_hh_f  = (const float*)d_in[4];
    const float* b_f     = (const float*)d_in[5];
    const float* W_ih_b  = (const float*)d_in[6];
    const float* W_hh_b  = (const float*)d_in[7];
    const float* b_b     = (const float*)d_in[8];
    const float* h0      = (const float*)d_in[9];
    const float* c0      = (const float*)d_in[10];
    const float* W_out   = (const float*)d_in[11];
    const float* b_out   = (const float*)d_in[12];
    const float* trans   = (const float*)d_in[13];
    float* out = (float*)d_out;

    const int SMEM_LSTM = (16 * SWS * 2 + 2 * 4 * 64 * 64) * 4;   // 196,736 B
    cudaFuncSetAttribute(lstm_persistent,
                         cudaFuncAttributeMaxDynamicSharedMemorySize, SMEM_LSTM);

    prep_kernel<<<1024, 256>>>(W_ih_f, W_ih_b, h0, W_out);
    xw_gemm<<<dim3(GATES / 128, SEQ, 2), 256>>>(tokens, W_emb, b_f, b_b);
    lstm_persistent<<<128, 512, SMEM_LSTM>>>(W_hh_f, W_hh_b, c0);
    feats_kernel<<<SEQ, 256>>>(b_out);
    crf_kernel<<<8, 96>>>(lengths, trans);
    crf_finish<<<1, 1>>>(out);
}

// round 9
// speedup vs baseline: 1.4470x; 1.4470x over previous
#include <cuda_runtime.h>
#include <math.h>

#define SEQ   512
#define BATCH 64
#define EMB   300
#define HID   512
#define GATES 2048   // 4*HID
#define NTAG  12
#define NEGV  (-10000.0f)
#define START_TAG 10
#define STOP_TAG  11

// ---------------- scratch (device globals; no allocation) ----------------
__device__ float g_xw[2][SEQ][GATES][BATCH];   // pre-activations x@W_ih.T+b
__device__ float g_hf[SEQ][HID][BATCH];        // forward hidden states [s][u][b]
__device__ float g_hb[SEQ][HID][BATCH];        // backward hidden states in SCAN order
__device__ float g_hinit[2][HID][BATCH];       // transposed h0
__device__ float g_Wt_ih[2][EMB][GATES];       // W_ih transposed [e][j]
__device__ float g_Wout_t[2 * HID][NTAG];      // W_out transposed [k][t]
__device__ float g_feats[SEQ][BATCH][NTAG];
__device__ float g_crf_part[8];
__device__ unsigned g_cnt2[2];
__device__ unsigned g_gen2[2];

// ---------------- f32x2 helpers ----------------
__device__ __forceinline__ unsigned long long splat2(float x) {
    unsigned long long r; unsigned u = __float_as_uint(x);
    asm("mov.b64 %0, {%1, %1};" : "=l"(r) : "r"(u));
    return r;
}
__device__ __forceinline__ void ffma2(unsigned long long& d,
                                      unsigned long long a,
                                      unsigned long long b) {
    asm("fma.rn.f32x2 %0, %1, %2, %0;" : "+l"(d) : "l"(a), "l"(b));
}
__device__ __forceinline__ float2 unpack2(unsigned long long v) {
    unsigned lo, hi;
    asm("mov.b64 {%0, %1}, %2;" : "=r"(lo), "=r"(hi) : "l"(v));
    float2 f; f.x = __uint_as_float(lo); f.y = __uint_as_float(hi);
    return f;
}
__device__ __forceinline__ float sigf(float x) { return 1.f / (1.f + __expf(-x)); }
__device__ __forceinline__ float tanhfast(float x) { return 2.f / (1.f + __expf(-2.f * x)) - 1.f; }

__device__ __forceinline__ unsigned ld_acq(const unsigned* p) {
    unsigned v;
    asm volatile("ld.acquire.gpu.global.u32 %0, [%1];" : "=r"(v) : "l"(p) : "memory");
    return v;
}

// ---------------- prep: transposes + state init + barrier reset ----------------
__global__ void prep_kernel(const float* Wif, const float* Wib, const float* h0,
                            const float* Wout) {
    if (blockIdx.x == 0 && threadIdx.x < 2) {
        g_cnt2[threadIdx.x] = 0;
        g_gen2[threadIdx.x] = 0;
    }
    const int N_IH = 2 * EMB * GATES;
    const int N_H  = 2 * HID * BATCH;
    const int N_WO = NTAG * 2 * HID;
    const int total = N_IH + N_H + N_WO;
    for (int idx = blockIdx.x * blockDim.x + threadIdx.x; idx < total;
         idx += gridDim.x * blockDim.x) {
        int i = idx;
        if (i < N_IH) {
            int d = i / (EMB * GATES);
            int r = i % (EMB * GATES);
            int e = r / GATES, j = r % GATES;
            const float* W = d ? Wib : Wif;
            g_Wt_ih[d][e][j] = W[j * EMB + e];
        } else if ((i -= N_IH) < N_H) {
            int d = i / (HID * BATCH);
            int r = i % (HID * BATCH);
            int u = r / BATCH, b = r % BATCH;
            g_hinit[d][u][b] = h0[(d * BATCH + b) * HID + u];
        } else {
            i -= N_H;
            int k = i / NTAG, t = i % NTAG;
            g_Wout_t[k][t] = Wout[t * (2 * HID) + k];
        }
    }
}

// ---------------- input GEMM (f32x2) ----------------
__global__ __launch_bounds__(256)
void xw_gemm(const int* __restrict__ tokens,
             const float* __restrict__ W_emb,
             const float* __restrict__ b_f,
             const float* __restrict__ b_b) {
    int dir = blockIdx.z;
    int s   = blockIdx.y;
    int n0  = blockIdx.x * 128;
    __shared__ float As[16][64];
    __shared__ float Bs[16][128];
    __shared__ int   tokS[64];
    int tid = threadIdx.x;
    if (tid < 64) {
        int srow = dir ? (SEQ - 1 - s) : s;
        tokS[tid] = tokens[tid * SEQ + srow];
    }
    __syncthreads();
    int c0 = (tid >> 3) * 4;
    int b0 = (tid & 7) * 8;
    unsigned long long acc[4][4] = {};
    for (int k0 = 0; k0 < 304; k0 += 16) {
        {
            int b = tid & 63, kk4 = (tid >> 6) * 4;
            int k = k0 + kk4;
            float4 v = {0.f, 0.f, 0.f, 0.f};
            if (k + 3 < EMB)
                v = *(const float4*)(W_emb + (size_t)tokS[b] * EMB + k);
            As[kk4 + 0][b] = v.x;
            As[kk4 + 1][b] = v.y;
            As[kk4 + 2][b] = v.z;
            As[kk4 + 3][b] = v.w;
        }
#pragma unroll
        for (int r = 0; r < 2; r++) {
            int idx = tid + 256 * r;
            int kk = idx >> 5, cg = idx & 31;
            float4 w = {0.f, 0.f, 0.f, 0.f};
            if (k0 + kk < EMB)
                w = *(const float4*)&g_Wt_ih[dir][k0 + kk][n0 + cg * 4];
            *(float4*)&Bs[kk][cg * 4] = w;
        }
        __syncthreads();
#pragma unroll
        for (int kk = 0; kk < 16; kk++) {
            float4 wv = *(const float4*)&Bs[kk][c0];
            unsigned long long w0 = splat2(wv.x), w1 = splat2(wv.y);
            unsigned long long w2 = splat2(wv.z), w3 = splat2(wv.w);
            ulonglong2 xA = *(const ulonglong2*)&As[kk][b0];
            ulonglong2 xB = *(const ulonglong2*)&As[kk][b0 + 4];
            ffma2(acc[0][0], xA.x, w0); ffma2(acc[0][1], xA.y, w0);
            ffma2(acc[0][2], xB.x, w0); ffma2(acc[0][3], xB.y, w0);
            ffma2(acc[1][0], xA.x, w1); ffma2(acc[1][1], xA.y, w1);
            ffma2(acc[1][2], xB.x, w1); ffma2(acc[1][3], xB.y, w1);
            ffma2(acc[2][0], xA.x, w2); ffma2(acc[2][1], xA.y, w2);
            ffma2(acc[2][2], xB.x, w2); ffma2(acc[2][3], xB.y, w2);
            ffma2(acc[3][0], xA.x, w3); ffma2(acc[3][1], xA.y, w3);
            ffma2(acc[3][2], xB.x, w3); ffma2(acc[3][3], xB.y, w3);
        }
        __syncthreads();
    }
    const float* bias = dir ? b_b : b_f;
#pragma unroll
    for (int cc = 0; cc < 4; cc++) {
        int j = n0 + c0 + cc;
        float bv = bias[j];
        float2 p0 = unpack2(acc[cc][0]), p1 = unpack2(acc[cc][1]);
        float2 p2 = unpack2(acc[cc][2]), p3 = unpack2(acc[cc][3]);
        float4 o0 = {p0.x + bv, p0.y + bv, p1.x + bv, p1.y + bv};
        float4 o1 = {p2.x + bv, p2.y + bv, p3.x + bv, p3.y + bv};
        *(float4*)&g_xw[dir][s][j][b0] = o0;
        *(float4*)&g_xw[dir][s][j][b0 + 4] = o1;
    }
}

// ---------------- persistent fused BiLSTM (R6 structure, pre-splatted W) ----------
// 128 blocks (64/dir) x 256 thr. Block = 8 units x 4 gates (32 cols) x 64 batch.
// W stored pre-splatted: sWs[col][k] = (w,w) as u64 -> LDS.64 yields FFMA2 operand
// directly (no MOV splats). h double-buffered in 128k-chunks. Per-direction
// acq_rel grid barrier.
#define SWSP 513                        // u64 per col row (512 + 1 pad)
__global__ __launch_bounds__(256, 1)
void lstm_persistent(const float* __restrict__ Whf, const float* __restrict__ Whb,
                     const float* __restrict__ c0in) {
    extern __shared__ float smem[];
    unsigned long long* sWs = (unsigned long long*)smem;  // [32 col][SWSP] u64 = 131,328 B
    float* sH = smem + 32 * SWSP * 2;                      // two 128x64 h chunks = 65,536 B
    __shared__ float sG[32 * 68];                          // gate exchange

    int tid = threadIdx.x;
    int bid = blockIdx.x;
    int dir = bid >> 6;
    int u0  = (bid & 63) * 8;
    const float* Whh = dir ? Whb : Whf;

    // stage W pre-splatted: sWs[c][k] = (W[jc][k], W[jc][k])
    for (int l = tid; l < 32 * 512; l += 256) {
        int c = l >> 9, k = l & 511;
        int j = (c >> 3) * HID + u0 + (c & 7);
        float w = Whh[j * HID + k];
        sWs[c * SWSP + k] = splat2(w);
    }

    int cp  = (tid >> 3) & 15;
    int c0i = cp * 2;
    int b0  = (tid & 7) * 4 + (tid >> 7) * 32;

    float cst[2];
#pragma unroll
    for (int idx = 0; idx < 2; idx++) {
        int p = tid + 256 * idx;
        int uu = p >> 6, b = p & 63;
        cst[idx] = c0in[(dir * BATCH + b) * HID + (u0 + uu)];
    }
    __syncthreads();

    const unsigned long long* wrowA = sWs + (size_t)c0i * SWSP;
    const unsigned long long* wrowB = sWs + (size_t)(c0i + 1) * SWSP;
    int j0 = (c0i >> 3) * HID + u0 + (c0i & 7);
    int c1i = c0i + 1;
    int j1 = (c1i >> 3) * HID + u0 + (c1i & 7);

    for (int s = 0; s < SEQ; s++) {
        const float* hprev = (s == 0) ? &g_hinit[dir][0][0]
                                      : (dir ? &g_hb[s - 1][0][0] : &g_hf[s - 1][0][0]);
        // hoist xw loads (independent of h)
        float4 x0 = *(const float4*)&g_xw[dir][s][j0][b0];
        float4 x1 = *(const float4*)&g_xw[dir][s][j1][b0];

        // preload chunk 0 (128 k x 64 b = 8192 floats; 8 float4 per thread)
#pragma unroll
        for (int r = 0; r < 8; r++) {
            int m = tid + 256 * r;   // float4 index 0..2047
            float4 v = *(const float4*)(hprev + m * 4);
            *(float4*)(sH + m * 4) = v;
        }
        __syncthreads();

        unsigned long long a00 = 0, a01 = 0, a10 = 0, a11 = 0;
        int buf = 0;
#pragma unroll 1
        for (int ch = 0; ch < 4; ch++) {
            float4 pf[8];
            if (ch < 3) {
#pragma unroll
                for (int r = 0; r < 8; r++) {
                    int m = tid + 256 * r;
                    pf[r] = *(const float4*)(hprev + (ch + 1) * 8192 + m * 4);
                }
            }
            const float* hb_ = sH + buf * 8192;
            int k0 = ch * 128;
#pragma unroll 8
            for (int kk = 0; kk < 128; kk += 2) {
                unsigned long long wa0 = wrowA[k0 + kk];
                unsigned long long wa1 = wrowA[k0 + kk + 1];
                unsigned long long wb0 = wrowB[k0 + kk];
                unsigned long long wb1 = wrowB[k0 + kk + 1];
                ulonglong2 hA = *(const ulonglong2*)(hb_ + kk * BATCH + b0);
                ulonglong2 hB = *(const ulonglong2*)(hb_ + (kk + 1) * BATCH + b0);
                ffma2(a00, hA.x, wa0); ffma2(a01, hA.y, wa0);
                ffma2(a10, hA.x, wb0); ffma2(a11, hA.y, wb0);
                ffma2(a00, hB.x, wa1); ffma2(a01, hB.y, wa1);
                ffma2(a10, hB.x, wb1); ffma2(a11, hB.y, wb1);
            }
            if (ch < 3) {
#pragma unroll
                for (int r = 0; r < 8; r++) {
                    int m = tid + 256 * r;
                    *(float4*)(sH + (buf ^ 1) * 8192 + m * 4) = pf[r];
                }
            }
            __syncthreads();
            buf ^= 1;
        }

        // gates: add xw, park in shared for gate exchange
        {
            float2 v00 = unpack2(a00), v01 = unpack2(a01);
            float2 v10 = unpack2(a10), v11 = unpack2(a11);
            float4 o0 = {v00.x + x0.x, v00.y + x0.y, v01.x + x0.z, v01.y + x0.w};
            float4 o1 = {v10.x + x1.x, v10.y + x1.y, v11.x + x1.z, v11.y + x1.w};
            *(float4*)(sG + c0i * 68 + b0) = o0;
            *(float4*)(sG + c1i * 68 + b0) = o1;
        }
        __syncthreads();

        // pointwise: 8 units x 64 batch; c stays in registers
        float* hout = dir ? &g_hb[s][0][0] : &g_hf[s][0][0];
#pragma unroll
        for (int idx = 0; idx < 2; idx++) {
            int p = tid + 256 * idx;
            int uu = p >> 6, b = p & 63;
            float gi = sG[uu * 68 + b];
            float gf = sG[(8 + uu) * 68 + b];
            float gg = sG[(16 + uu) * 68 + b];
            float go = sG[(24 + uu) * 68 + b];
            float iv = sigf(gi), fv = sigf(gf), ov = sigf(go);
            float c = fv * cst[idx] + iv * tanhfast(gg);
            cst[idx] = c;
            hout[(u0 + uu) * BATCH + b] = ov * tanhfast(c);
        }
        __syncthreads();

        // per-direction grid barrier (skipped after the last step)
        if (s < SEQ - 1) {
            if (tid == 0) {
                unsigned target = (unsigned)(s + 1);
                unsigned prev;
                asm volatile("atom.acq_rel.gpu.global.add.u32 %0, [%1], 1;"
                             : "=r"(prev) : "l"(&g_cnt2[dir]) : "memory");
                if (prev == 63) {
                    asm volatile("st.relaxed.gpu.global.u32 [%0], %1;"
                                 :: "l"(&g_cnt2[dir]), "r"(0u) : "memory");
                    asm volatile("st.release.gpu.global.u32 [%0], %1;"
                                 :: "l"(&g_gen2[dir]), "r"(target) : "memory");
                } else {
                    unsigned g;
                    do { g = ld_acq(&g_gen2[dir]); } while (g < target);
                }
            }
            __syncthreads();
        }
    }
}

// ---------------- feats: K-split, 12 independent chains per thread ----------------
__global__ __launch_bounds__(256)
void feats_kernel(const float* __restrict__ b_out) {
    int s = blockIdx.x;
    int tid = threadIdx.x;
    int b = tid & 63;
    int slice = tid >> 6;
    __shared__ float sred[256][NTAG];
    float a[NTAG];
#pragma unroll
    for (int t = 0; t < NTAG; t++) a[t] = 0.f;

    int base = slice * 256;
    const float* hbase = (base < HID) ? &g_hf[s][base][0]
                                      : &g_hb[SEQ - 1 - s][base - HID][0];
#pragma unroll 4
    for (int k = 0; k < 256; k++) {
        float h = hbase[k * BATCH + b];
        int kg = base + k;
        float4 w0 = *(const float4*)&g_Wout_t[kg][0];
        float4 w1 = *(const float4*)&g_Wout_t[kg][4];
        float4 w2 = *(const float4*)&g_Wout_t[kg][8];
        a[0] += h * w0.x;  a[1] += h * w0.y;  a[2]  += h * w0.z;  a[3]  += h * w0.w;
        a[4] += h * w1.x;  a[5] += h * w1.y;  a[6]  += h * w1.z;  a[7]  += h * w1.w;
        a[8] += h * w2.x;  a[9] += h * w2.y;  a[10] += h * w2.z;  a[11] += h * w2.w;
    }
#pragma unroll
    for (int t = 0; t < NTAG; t++) sred[tid][t] = a[t];
    __syncthreads();
    if (tid < 64) {
#pragma unroll
        for (int t = 0; t < NTAG; t++) {
            float v = b_out[t] + sred[tid][t] + sred[64 + tid][t]
                    + sred[128 + tid][t] + sred[192 + tid][t];
            g_feats[s][tid][t] = v;
        }
    }
}

// ---------------- CRF forward: 8 blocks x 8 batches, feats prefetch ----------------
__global__ __launch_bounds__(96)
void crf_kernel(const int* __restrict__ lengths,
                const float* __restrict__ trans) {
    __shared__ float alpha[8][NTAG];
    __shared__ float tr[NTAG][NTAG];
    __shared__ float termS[8][NTAG];
    int tid = threadIdx.x;
    int b = tid / NTAG, t = tid % NTAG;
    int bg = blockIdx.x * 8 + b;
    for (int l = tid; l < NTAG * NTAG; l += 96)
        tr[l / NTAG][l % NTAG] = trans[l];
    alpha[b][t] = (t == START_TAG) ? 0.f : NEGV;
    int len = lengths[bg];
    __syncthreads();
    float fcur = g_feats[0][bg][t];
    for (int s = 0; s < SEQ; s++) {
        float fnext = (s + 1 < SEQ) ? g_feats[s + 1][bg][t] : 0.f;
        float v[NTAG];
        float mx = -1e30f;
#pragma unroll
        for (int p = 0; p < NTAG; p++) {
            v[p] = alpha[b][p] + tr[t][p];
            mx = fmaxf(mx, v[p]);
        }
        float sum = 0.f;
#pragma unroll
        for (int p = 0; p < NTAG; p++) sum += __expf(v[p] - mx);
        float newv = mx + __logf(sum) + fcur;
        float keep = alpha[b][t];
        float nv = (s < len) ? newv : keep;
        __syncthreads();
        alpha[b][t] = nv;
        __syncthreads();
        fcur = fnext;
    }
    termS[b][t] = alpha[b][t] + tr[STOP_TAG][t];
    __syncthreads();
    if (t == 0) {
        float mx = -1e30f;
#pragma unroll
        for (int p = 0; p < NTAG; p++) mx = fmaxf(mx, termS[b][p]);
        float sum = 0.f;
#pragma unroll
        for (int p = 0; p < NTAG; p++) sum += __expf(termS[b][p] - mx);
        termS[b][0] = mx + __logf(sum);
    }
    __syncthreads();
    if (tid == 0) {
        float s2 = 0.f;
        for (int i = 0; i < 8; i++) s2 += termS[i][0];
        g_crf_part[blockIdx.x] = s2;
    }
}

__global__ void crf_finish(float* __restrict__ out) {
    float s = 0.f;
    for (int i = 0; i < 8; i++) s += g_crf_part[i];
    out[0] = s / (float)BATCH;
}

// ---------------- launch ----------------
extern "C" void kernel_launch(void* const* d_in, const int* in_sizes, int n_in,
                              void* d_out, int out_size) {
    const int*   tokens  = (const int*)  d_in[0];
    const int*   lengths = (const int*)  d_in[1];
    const float* W_emb   = (const float*)d_in[2];
    const float* W_ih_f  = (const float*)d_in[3];
    const float* W_hh_f  = (const float*)d_in[4];
    const float* b_f     = (const float*)d_in[5];
    const float* W_ih_b  = (const float*)d_in[6];
    const float* W_hh_b  = (const float*)d_in[7];
    const float* b_b     = (const float*)d_in[8];
    const float* h0      = (const float*)d_in[9];
    const float* c0      = (const float*)d_in[10];
    const float* W_out   = (const float*)d_in[11];
    const float* b_out   = (const float*)d_in[12];
    const float* trans   = (const float*)d_in[13];
    float* out = (float*)d_out;

    const int SMEM_LSTM = 32 * SWSP * 8 + 2 * 128 * 64 * 4;   // 196,864 B
    cudaFuncSetAttribute(lstm_persistent,
                         cudaFuncAttributeMaxDynamicSharedMemorySize, SMEM_LSTM);

    prep_kernel<<<1024, 256>>>(W_ih_f, W_ih_b, h0, W_out);
    xw_gemm<<<dim3(GATES / 128, SEQ, 2), 256>>>(tokens, W_emb, b_f, b_b);
    lstm_persistent<<<128, 256, SMEM_LSTM>>>(W_hh_f, W_hh_b, c0);
    feats_kernel<<<SEQ, 256>>>(b_out);
    crf_kernel<<<8, 96>>>(lengths, trans);
    crf_finish<<<1, 1>>>(out);
}

// round 10
// speedup vs baseline: 1.6401x; 1.1334x over previous
#include <cuda_runtime.h>
#include <math.h>

#define SEQ   512
#define BATCH 64
#define EMB   300
#define HID   512
#define GATES 2048   // 4*HID
#define NTAG  12
#define NEGV  (-10000.0f)
#define START_TAG 10
#define STOP_TAG  11

// ---------------- scratch (device globals; no allocation) ----------------
__device__ float g_xw[2][SEQ][GATES][BATCH];   // pre-activations x@W_ih.T+b
__device__ float g_hf[SEQ][HID][BATCH];        // forward hidden states [s][u][b]
__device__ float g_hb[SEQ][HID][BATCH];        // backward hidden states in SCAN order
__device__ float g_hinit[2][HID][BATCH];       // transposed h0
__device__ float g_Wt_ih[2][EMB][GATES];       // W_ih transposed [e][j]
__device__ float g_Wout_t[2 * HID][NTAG];      // W_out transposed [k][t]
__device__ float g_feats[SEQ][BATCH][NTAG];
__device__ float g_crf_part[8];
__device__ unsigned g_cnt2[2];
__device__ unsigned g_gen2[2];

// ---------------- f32x2 helpers ----------------
__device__ __forceinline__ unsigned long long splat2(float x) {
    unsigned long long r; unsigned u = __float_as_uint(x);
    asm("mov.b64 %0, {%1, %1};" : "=l"(r) : "r"(u));
    return r;
}
__device__ __forceinline__ void ffma2(unsigned long long& d,
                                      unsigned long long a,
                                      unsigned long long b) {
    asm("fma.rn.f32x2 %0, %1, %2, %0;" : "+l"(d) : "l"(a), "l"(b));
}
__device__ __forceinline__ unsigned long long addf2(unsigned long long a,
                                                    unsigned long long b) {
    unsigned long long r;
    asm("add.rn.f32x2 %0, %1, %2;" : "=l"(r) : "l"(a), "l"(b));
    return r;
}
__device__ __forceinline__ float2 unpack2(unsigned long long v) {
    unsigned lo, hi;
    asm("mov.b64 {%0, %1}, %2;" : "=r"(lo), "=r"(hi) : "l"(v));
    float2 f; f.x = __uint_as_float(lo); f.y = __uint_as_float(hi);
    return f;
}
__device__ __forceinline__ float sigf(float x) { return 1.f / (1.f + __expf(-x)); }
__device__ __forceinline__ float tanhfast(float x) { return 2.f / (1.f + __expf(-2.f * x)) - 1.f; }

__device__ __forceinline__ unsigned ld_acq(const unsigned* p) {
    unsigned v;
    asm volatile("ld.acquire.gpu.global.u32 %0, [%1];" : "=r"(v) : "l"(p) : "memory");
    return v;
}

// ---------------- prep: transposes + state init + barrier reset ----------------
__global__ void prep_kernel(const float* Wif, const float* Wib, const float* h0,
                            const float* Wout) {
    if (blockIdx.x == 0 && threadIdx.x < 2) {
        g_cnt2[threadIdx.x] = 0;
        g_gen2[threadIdx.x] = 0;
    }
    const int N_IH = 2 * EMB * GATES;
    const int N_H  = 2 * HID * BATCH;
    const int N_WO = NTAG * 2 * HID;
    const int total = N_IH + N_H + N_WO;
    for (int idx = blockIdx.x * blockDim.x + threadIdx.x; idx < total;
         idx += gridDim.x * blockDim.x) {
        int i = idx;
        if (i < N_IH) {
            int d = i / (EMB * GATES);
            int r = i % (EMB * GATES);
            int e = r / GATES, j = r % GATES;
            const float* W = d ? Wib : Wif;
            g_Wt_ih[d][e][j] = W[j * EMB + e];
        } else if ((i -= N_IH) < N_H) {
            int d = i / (HID * BATCH);
            int r = i % (HID * BATCH);
            int u = r / BATCH, b = r % BATCH;
            g_hinit[d][u][b] = h0[(d * BATCH + b) * HID + u];
        } else {
            i -= N_H;
            int k = i / NTAG, t = i % NTAG;
            g_Wout_t[k][t] = Wout[t * (2 * HID) + k];
        }
    }
}

// ---------------- input GEMM (f32x2) ----------------
__global__ __launch_bounds__(256)
void xw_gemm(const int* __restrict__ tokens,
             const float* __restrict__ W_emb,
             const float* __restrict__ b_f,
             const float* __restrict__ b_b) {
    int dir = blockIdx.z;
    int s   = blockIdx.y;
    int n0  = blockIdx.x * 128;
    __shared__ float As[16][64];
    __shared__ float Bs[16][128];
    __shared__ int   tokS[64];
    int tid = threadIdx.x;
    if (tid < 64) {
        int srow = dir ? (SEQ - 1 - s) : s;
        tokS[tid] = tokens[tid * SEQ + srow];
    }
    __syncthreads();
    int c0 = (tid >> 3) * 4;
    int b0 = (tid & 7) * 8;
    unsigned long long acc[4][4] = {};
    for (int k0 = 0; k0 < 304; k0 += 16) {
        {
            int b = tid & 63, kk4 = (tid >> 6) * 4;
            int k = k0 + kk4;
            float4 v = {0.f, 0.f, 0.f, 0.f};
            if (k + 3 < EMB)
                v = *(const float4*)(W_emb + (size_t)tokS[b] * EMB + k);
            As[kk4 + 0][b] = v.x;
            As[kk4 + 1][b] = v.y;
            As[kk4 + 2][b] = v.z;
            As[kk4 + 3][b] = v.w;
        }
#pragma unroll
        for (int r = 0; r < 2; r++) {
            int idx = tid + 256 * r;
            int kk = idx >> 5, cg = idx & 31;
            float4 w = {0.f, 0.f, 0.f, 0.f};
            if (k0 + kk < EMB)
                w = *(const float4*)&g_Wt_ih[dir][k0 + kk][n0 + cg * 4];
            *(float4*)&Bs[kk][cg * 4] = w;
        }
        __syncthreads();
#pragma unroll
        for (int kk = 0; kk < 16; kk++) {
            float4 wv = *(const float4*)&Bs[kk][c0];
            unsigned long long w0 = splat2(wv.x), w1 = splat2(wv.y);
            unsigned long long w2 = splat2(wv.z), w3 = splat2(wv.w);
            ulonglong2 xA = *(const ulonglong2*)&As[kk][b0];
            ulonglong2 xB = *(const ulonglong2*)&As[kk][b0 + 4];
            ffma2(acc[0][0], xA.x, w0); ffma2(acc[0][1], xA.y, w0);
            ffma2(acc[0][2], xB.x, w0); ffma2(acc[0][3], xB.y, w0);
            ffma2(acc[1][0], xA.x, w1); ffma2(acc[1][1], xA.y, w1);
            ffma2(acc[1][2], xB.x, w1); ffma2(acc[1][3], xB.y, w1);
            ffma2(acc[2][0], xA.x, w2); ffma2(acc[2][1], xA.y, w2);
            ffma2(acc[2][2], xB.x, w2); ffma2(acc[2][3], xB.y, w2);
            ffma2(acc[3][0], xA.x, w3); ffma2(acc[3][1], xA.y, w3);
            ffma2(acc[3][2], xB.x, w3); ffma2(acc[3][3], xB.y, w3);
        }
        __syncthreads();
    }
    const float* bias = dir ? b_b : b_f;
#pragma unroll
    for (int cc = 0; cc < 4; cc++) {
        int j = n0 + c0 + cc;
        float bv = bias[j];
        float2 p0 = unpack2(acc[cc][0]), p1 = unpack2(acc[cc][1]);
        float2 p2 = unpack2(acc[cc][2]), p3 = unpack2(acc[cc][3]);
        float4 o0 = {p0.x + bv, p0.y + bv, p1.x + bv, p1.y + bv};
        float4 o1 = {p2.x + bv, p2.y + bv, p3.x + bv, p3.y + bv};
        *(float4*)&g_xw[dir][s][j][b0] = o0;
        *(float4*)&g_xw[dir][s][j][b0 + 4] = o1;
    }
}

// ---------------- persistent fused BiLSTM (512 thr, 2-way K-split, R6 barrier) ----
// 128 blocks (64/dir) x 512 thr. Block = 8 units x 4 gates (32 cols) x 64 batch.
// Thread = 2 cols x 4 batch x 256 k (kg = tid>>8). Whole h staged once per step.
#define SWS 513
__global__ __launch_bounds__(512, 1)
void lstm_persistent(const float* __restrict__ Whf, const float* __restrict__ Whb,
                     const float* __restrict__ c0in) {
    extern __shared__ float smem[];
    float2* sW = (float2*)smem;               // [16 cp][SWS] float2 = 65,664 B
    float*  sH = smem + 16 * SWS * 2;         // full h: 512 k x 64 b = 131,072 B
    // reduction park + gate exchange alias dead sH regions after compute:
    //   park: sH bytes [0, 8192); gates: sH floats [2048, 2048+2176)

    int tid = threadIdx.x;
    int bid = blockIdx.x;
    int dir = bid >> 6;
    int u0  = (bid & 63) * 8;
    const float* Whh = dir ? Whb : Whf;

    // stage W pairs: sW[cp][k] = (W[col 2cp][k], W[col 2cp+1][k])
    for (int l = tid; l < 16 * 512; l += 512) {
        int cp = l >> 9, k = l & 511;
        int ca = cp * 2, cb = ca + 1;
        int ja = (ca >> 3) * HID + u0 + (ca & 7);
        int jb = (cb >> 3) * HID + u0 + (cb & 7);
        float2 v;
        v.x = Whh[ja * HID + k];
        v.y = Whh[jb * HID + k];
        sW[cp * SWS + k] = v;
    }

    int kg  = tid >> 8;                          // 0 or 1 (k-half)
    int lo  = tid & 255;
    int cp  = (lo >> 3) & 15;                    // col-pair 0..15
    int c0i = cp * 2;
    int b0  = (lo & 7) * 4 + ((lo >> 7) & 1) * 32;  // batch base, 4 per thread

    float cst;                                   // 1 cell elem per thread
    {
        int uu = tid >> 6 & 7, b = tid & 63;
        cst = c0in[(dir * BATCH + b) * HID + (u0 + uu)];
    }
    __syncthreads();

    const float2* wrow = sW + cp * SWS;
    int j0 = (c0i >> 3) * HID + u0 + (c0i & 7);
    int c1i = c0i + 1;
    int j1 = (c1i >> 3) * HID + u0 + (c1i & 7);
    int k0 = kg * 256;

    for (int s = 0; s < SEQ; s++) {
        const float* hprev = (s == 0) ? &g_hinit[dir][0][0]
                                      : (dir ? &g_hb[s - 1][0][0] : &g_hf[s - 1][0][0]);
        // hoist xw loads (kg==0 only; warp-uniform branch)
        float4 x0, x1;
        if (kg == 0) {
            x0 = *(const float4*)&g_xw[dir][s][j0][b0];
            x1 = *(const float4*)&g_xw[dir][s][j1][b0];
        }

        // stage whole h: 32768 floats = 8192 f4; 16 f4/thread
#pragma unroll
        for (int r = 0; r < 16; r++) {
            int m = tid + 512 * r;
            float4 v = *(const float4*)(hprev + m * 4);
            *(float4*)(sH + m * 4) = v;
        }
        __syncthreads();

        // compute this k-half: 128 iterations of 2 k
        unsigned long long a00 = 0, a01 = 0, a10 = 0, a11 = 0;
#pragma unroll 8
        for (int kk = k0; kk < k0 + 256; kk += 2) {
            float2 wA = wrow[kk];
            float2 wB = wrow[kk + 1];
            unsigned long long hA0 = *(const unsigned long long*)(sH + kk * BATCH + b0);
            unsigned long long hA1 = *(const unsigned long long*)(sH + kk * BATCH + b0 + 2);
            unsigned long long hB0 = *(const unsigned long long*)(sH + (kk + 1) * BATCH + b0);
            unsigned long long hB1 = *(const unsigned long long*)(sH + (kk + 1) * BATCH + b0 + 2);
            unsigned long long wa0 = splat2(wA.x), wa1 = splat2(wA.y);
            unsigned long long wb0 = splat2(wB.x), wb1 = splat2(wB.y);
            ffma2(a00, hA0, wa0); ffma2(a01, hA1, wa0);
            ffma2(a10, hA0, wa1); ffma2(a11, hA1, wa1);
            ffma2(a00, hB0, wb0); ffma2(a01, hB1, wb0);
            ffma2(a10, hB0, wb1); ffma2(a11, hB1, wb1);
        }
        __syncthreads();   // everyone done reading sH

        // K-split reduce: kg1 parks 4 u64 at slot lo (32B/thread, conflict-free)
        if (kg == 1) {
            ulonglong2* pp = (ulonglong2*)((unsigned long long*)sH + (size_t)lo * 4);
            pp[0] = make_ulonglong2(a00, a01);
            pp[1] = make_ulonglong2(a10, a11);
        }
        __syncthreads();

        float* sG = sH + 2048;                   // gates region (beyond 8KB park)
        if (kg == 0) {
            const ulonglong2* pp = (const ulonglong2*)((unsigned long long*)sH + (size_t)lo * 4);
            ulonglong2 v0 = pp[0], v1 = pp[1];
            a00 = addf2(a00, v0.x); a01 = addf2(a01, v0.y);
            a10 = addf2(a10, v1.x); a11 = addf2(a11, v1.y);
            float2 p0 = unpack2(a00), p1 = unpack2(a01);
            float2 q0 = unpack2(a10), q1 = unpack2(a11);
            float4 o0 = {p0.x + x0.x, p0.y + x0.y, p1.x + x0.z, p1.y + x0.w};
            float4 o1 = {q0.x + x1.x, q0.y + x1.y, q1.x + x1.z, q1.y + x1.w};
            *(float4*)(sG + c0i * 68 + b0) = o0;
            *(float4*)(sG + c1i * 68 + b0) = o1;
        }
        __syncthreads();

        // pointwise: 1 elem/thread (8 units x 64 batch); c in registers
        float* hout = dir ? &g_hb[s][0][0] : &g_hf[s][0][0];
        {
            int uu = tid >> 6 & 7, b = tid & 63;
            float gi = sG[uu * 68 + b];
            float gf = sG[(8 + uu) * 68 + b];
            float gg = sG[(16 + uu) * 68 + b];
            float go = sG[(24 + uu) * 68 + b];
            float iv = sigf(gi), fv = sigf(gf), ov = sigf(go);
            float c = fv * cst + iv * tanhfast(gg);
            cst = c;
            hout[(u0 + uu) * BATCH + b] = ov * tanhfast(c);
        }
        __syncthreads();

        // per-direction grid barrier (R6-proven), skipped after last step
        if (s < SEQ - 1) {
            if (tid == 0) {
                unsigned target = (unsigned)(s + 1);
                unsigned prev;
                asm volatile("atom.acq_rel.gpu.global.add.u32 %0, [%1], 1;"
                             : "=r"(prev) : "l"(&g_cnt2[dir]) : "memory");
                if (prev == 63) {
                    asm volatile("st.relaxed.gpu.global.u32 [%0], %1;"
                                 :: "l"(&g_cnt2[dir]), "r"(0u) : "memory");
                    asm volatile("st.release.gpu.global.u32 [%0], %1;"
                                 :: "l"(&g_gen2[dir]), "r"(target) : "memory");
                } else {
                    unsigned g;
                    do { g = ld_acq(&g_gen2[dir]); } while (g < target);
                }
            }
            __syncthreads();
        }
    }
}

// ---------------- feats: K-split, 12 independent chains per thread ----------------
__global__ __launch_bounds__(256)
void feats_kernel(const float* __restrict__ b_out) {
    int s = blockIdx.x;
    int tid = threadIdx.x;
    int b = tid & 63;
    int slice = tid >> 6;
    __shared__ float sred[256][NTAG];
    float a[NTAG];
#pragma unroll
    for (int t = 0; t < NTAG; t++) a[t] = 0.f;

    int base = slice * 256;
    const float* hbase = (base < HID) ? &g_hf[s][base][0]
                                      : &g_hb[SEQ - 1 - s][base - HID][0];
#pragma unroll 4
    for (int k = 0; k < 256; k++) {
        float h = hbase[k * BATCH + b];
        int kg = base + k;
        float4 w0 = *(const float4*)&g_Wout_t[kg][0];
        float4 w1 = *(const float4*)&g_Wout_t[kg][4];
        float4 w2 = *(const float4*)&g_Wout_t[kg][8];
        a[0] += h * w0.x;  a[1] += h * w0.y;  a[2]  += h * w0.z;  a[3]  += h * w0.w;
        a[4] += h * w1.x;  a[5] += h * w1.y;  a[6]  += h * w1.z;  a[7]  += h * w1.w;
        a[8] += h * w2.x;  a[9] += h * w2.y;  a[10] += h * w2.z;  a[11] += h * w2.w;
    }
#pragma unroll
    for (int t = 0; t < NTAG; t++) sred[tid][t] = a[t];
    __syncthreads();
    if (tid < 64) {
#pragma unroll
        for (int t = 0; t < NTAG; t++) {
            float v = b_out[t] + sred[tid][t] + sred[64 + tid][t]
                    + sred[128 + tid][t] + sred[192 + tid][t];
            g_feats[s][tid][t] = v;
        }
    }
}

// ---------------- CRF forward: 8 blocks x 8 batches, feats prefetch ----------------
__global__ __launch_bounds__(96)
void crf_kernel(const int* __restrict__ lengths,
                const float* __restrict__ trans) {
    __shared__ float alpha[8][NTAG];
    __shared__ float tr[NTAG][NTAG];
    __shared__ float termS[8][NTAG];
    int tid = threadIdx.x;
    int b = tid / NTAG, t = tid % NTAG;
    int bg = blockIdx.x * 8 + b;
    for (int l = tid; l < NTAG * NTAG; l += 96)
        tr[l / NTAG][l % NTAG] = trans[l];
    alpha[b][t] = (t == START_TAG) ? 0.f : NEGV;
    int len = lengths[bg];
    __syncthreads();
    float fcur = g_feats[0][bg][t];
    for (int s = 0; s < SEQ; s++) {
        float fnext = (s + 1 < SEQ) ? g_feats[s + 1][bg][t] : 0.f;
        float v[NTAG];
        float mx = -1e30f;
#pragma unroll
        for (int p = 0; p < NTAG; p++) {
            v[p] = alpha[b][p] + tr[t][p];
            mx = fmaxf(mx, v[p]);
        }
        float sum = 0.f;
#pragma unroll
        for (int p = 0; p < NTAG; p++) sum += __expf(v[p] - mx);
        float newv = mx + __logf(sum) + fcur;
        float keep = alpha[b][t];
        float nv = (s < len) ? newv : keep;
        __syncthreads();
        alpha[b][t] = nv;
        __syncthreads();
        fcur = fnext;
    }
    termS[b][t] = alpha[b][t] + tr[STOP_TAG][t];
    __syncthreads();
    if (t == 0) {
        float mx = -1e30f;
#pragma unroll
        for (int p = 0; p < NTAG; p++) mx = fmaxf(mx, termS[b][p]);
        float sum = 0.f;
#pragma unroll
        for (int p = 0; p < NTAG; p++) sum += __expf(termS[b][p] - mx);
        termS[b][0] = mx + __logf(sum);
    }
    __syncthreads();
    if (tid == 0) {
        float s2 = 0.f;
        for (int i = 0; i < 8; i++) s2 += termS[i][0];
        g_crf_part[blockIdx.x] = s2;
    }
}

__global__ void crf_finish(float* __restrict__ out) {
    float s = 0.f;
    for (int i = 0; i < 8; i++) s += g_crf_part[i];
    out[0] = s / (float)BATCH;
}

// ---------------- launch ----------------
extern "C" void kernel_launch(void* const* d_in, const int* in_sizes, int n_in,
                              void* d_out, int out_size) {
    const int*   tokens  = (const int*)  d_in[0];
    const int*   lengths = (const int*)  d_in[1];
    const float* W_emb   = (const float*)d_in[2];
    const float* W_ih_f  = (const float*)d_in[3];
    const float* W_hh_f  = (const float*)d_in[4];
    const float* b_f     = (const float*)d_in[5];
    const float* W_ih_b  = (const float*)d_in[6];
    const float* W_hh_b  = (const float*)d_in[7];
    const float* b_b     = (const float*)d_in[8];
    const float* h0      = (const float*)d_in[9];
    const float* c0      = (const float*)d_in[10];
    const float* W_out   = (const float*)d_in[11];
    const float* b_out   = (const float*)d_in[12];
    const float* trans   = (const float*)d_in[13];
    float* out = (float*)d_out;

    const int SMEM_LSTM = (16 * SWS * 2 + HID * BATCH) * 4;   // 196,736 B
    cudaFuncSetAttribute(lstm_persistent,
                         cudaFuncAttributeMaxDynamicSharedMemorySize, SMEM_LSTM);

    prep_kernel<<<1024, 256>>>(W_ih_f, W_ih_b, h0, W_out);
    xw_gemm<<<dim3(GATES / 128, SEQ, 2), 256>>>(tokens, W_emb, b_f, b_b);
    lstm_persistent<<<128, 512, SMEM_LSTM>>>(W_hh_f, W_hh_b, c0);
    feats_kernel<<<SEQ, 256>>>(b_out);
    crf_kernel<<<8, 96>>>(lengths, trans);
    crf_finish<<<1, 1>>>(out);
}